// round 1
// baseline (speedup 1.0000x reference)
#include <cuda_runtime.h>
#include <cuda_bf16.h>
#include <math.h>

// Problem constants
#define B_    8
#define N_    128
#define K_    16
#define ALPHA 0.01f
#define LAM   1.0f
#define KAPPA 1.0f
#define EPS   1e-6f

#define NODES (B_ * N_)   // 1024

// Scratch (device globals — no allocation allowed)
__device__ float E_g[NODES * K_ * K_];   // exp(phi.G) per node, row-major
__device__ float M_g[NODES * K_ * K_];   // E^T diag(1/(sq+eps)) E per node
__device__ float u_g[NODES * K_];        // E^T mu_q per node

// ---------------------------------------------------------------------------
// Kernel 1: per-node precompute.
// A = sum_a phi[a] * G[a]  (antisymmetric 16x16)
// E = expm(A) via scaling-and-squaring + Taylor(13)
// u = E^T mu_q,  M = E^T diag(1/(clip(sigma_q)+eps)) E
// Block = 256 threads (one per matrix element), grid = 1024 nodes.
// ---------------------------------------------------------------------------
__global__ __launch_bounds__(256, 4)
void prep_kernel(const float* __restrict__ mu_q,
                 const float* __restrict__ sigma_q,
                 const float* __restrict__ phi,
                 const float* __restrict__ gen)
{
    const int node = blockIdx.x;
    const int tid  = threadIdx.x;          // 0..255
    const int r = tid >> 4, c = tid & 15;

    __shared__ float A [16][17];
    __shared__ float X [16][17];
    __shared__ float Y [16][17];
    __shared__ float rowsum[16];
    __shared__ int   s_shift;
    __shared__ float dinv[16];
    __shared__ float mush[16];

    const float p0 = __ldg(&phi[node*3 + 0]);
    const float p1 = __ldg(&phi[node*3 + 1]);
    const float p2 = __ldg(&phi[node*3 + 2]);
    const float a_raw = p0 * __ldg(&gen[0*256 + tid])
                      + p1 * __ldg(&gen[1*256 + tid])
                      + p2 * __ldg(&gen[2*256 + tid]);
    A[r][c] = a_raw;
    __syncthreads();

    // inf-norm for scaling
    if (tid < 16) {
        float s = 0.f;
        #pragma unroll
        for (int l = 0; l < 16; l++) s += fabsf(A[tid][l]);
        rowsum[tid] = s;
    }
    __syncthreads();
    if (tid == 0) {
        float nrm = 0.f;
        #pragma unroll
        for (int l = 0; l < 16; l++) nrm = fmaxf(nrm, rowsum[l]);
        int s = 0;
        while (nrm > 0.5f && s < 30) { nrm *= 0.5f; s++; }
        s_shift = s;
    }
    __syncthreads();
    const int   s_sq  = s_shift;
    const float scale = ldexpf(1.0f, -s_sq);

    // scaled matrix (rowsum reads already synced past)
    A[r][c] = a_raw * scale;

    // Taylor-13 Horner:  X = I + B/13 ; X = I + (B/m) X, m = 12..1
    const int q = 13;
    __syncthreads();
    X[r][c] = (r == c ? 1.0f : 0.0f) + A[r][c] * (1.0f / (float)q);
    __syncthreads();

    float* Xp = &X[0][0];
    float* Yp = &Y[0][0];
    for (int m = q - 1; m >= 1; m--) {
        const float inv = 1.0f / (float)m;
        float acc = 0.f;
        #pragma unroll
        for (int l = 0; l < 16; l++) acc += A[r][l] * Xp[l*17 + c];
        Yp[r*17 + c] = (r == c ? 1.0f : 0.0f) + inv * acc;
        __syncthreads();
        float* t = Xp; Xp = Yp; Yp = t;
    }

    // squaring
    for (int t = 0; t < s_sq; t++) {
        float acc = 0.f;
        #pragma unroll
        for (int l = 0; l < 16; l++) acc += Xp[r*17 + l] * Xp[l*17 + c];
        Yp[r*17 + c] = acc;
        __syncthreads();
        float* tt = Xp; Xp = Yp; Yp = tt;
    }
    // Xp == E (row-major in shared, stride 17)

    if (tid < 16) {
        const float sq = fmaxf(__ldg(&sigma_q[node*16 + tid]), EPS);
        dinv[tid] = 1.0f / (sq + EPS);
        mush[tid] = __ldg(&mu_q[node*16 + tid]);
    }
    __syncthreads();

    // M = E^T D^{-1} E
    {
        float acc = 0.f;
        #pragma unroll
        for (int l = 0; l < 16; l++) acc += Xp[l*17 + r] * dinv[l] * Xp[l*17 + c];
        M_g[node*256 + r*16 + c] = acc;
        E_g[node*256 + r*16 + c] = Xp[r*17 + c];
    }
    // u = E^T mu
    if (tid < 16) {
        float uu = 0.f;
        #pragma unroll
        for (int l = 0; l < 16; l++) uu += Xp[l*17 + tid] * mush[l];
        u_g[node*16 + tid] = uu;
    }
}

// ---------------------------------------------------------------------------
// Kernel 2: pair reduction. One block per (b, i); 128 threads = 8 half-warps.
// Each half-warp owns one j per iteration; lane-within-half = component k.
//   v_k   = sum_l M_j[k][l] (u_i[l]-u_j[l])
//   kl    = 0.5 * sum_k (u_i[k]-u_j[k]) v_k      (shfl-16 reduce)
//   S1   += beta_ij v ; S2 += beta_ij kl v ; s3 += beta_ij kl
// Epilogue: t = LAM*S1 + (LAM/KAPPA)*(S2 - s3*S1); grad_mu = self + E_i t.
// ---------------------------------------------------------------------------
__global__ __launch_bounds__(128, 8)
void pair_kernel(const float* __restrict__ mu_q,
                 const float* __restrict__ sigma_q,
                 const float* __restrict__ mu_p,
                 const float* __restrict__ sigma_p,
                 const float* __restrict__ beta,
                 float* __restrict__ out)
{
    const int blk = blockIdx.x;
    const int b   = blk >> 7;
    const int i   = blk & 127;
    const int tid = threadIdx.x;       // 0..127

    __shared__ float u_sh[N_ * K_];    // 8 KB: all u for this batch
    __shared__ float beta_sh[N_];
    __shared__ float red1[8][16];
    __shared__ float red2[8][16];
    __shared__ float red3[8];
    __shared__ float t_sh[16];

    const float* ub = u_g + b * N_ * K_;
    #pragma unroll
    for (int idx = tid; idx < N_ * K_; idx += 128) u_sh[idx] = ub[idx];
    beta_sh[tid] = __ldg(&beta[(b * N_ + i) * N_ + tid]);
    __syncthreads();

    float ui[16];
    #pragma unroll
    for (int l = 0; l < 16; l++) ui[l] = u_sh[i*16 + l];

    const int lane = tid & 31;
    const int warp = tid >> 5;         // 0..3
    const int half = (lane >> 4);      // 0/1
    const int k    = lane & 15;        // component
    const int hw   = tid >> 4;         // 0..7 half-warp id

    float s1 = 0.f, s2 = 0.f, s3 = 0.f;
    const float* Mb = M_g + b * N_ * 256;

    for (int iter = 0; iter < 16; iter++) {
        const int j = iter * 8 + warp * 2 + half;
        const float* Mj = Mb + j * 256 + k * 16;
        const float* uj = &u_sh[j * 16];

        float v = 0.f;
        #pragma unroll
        for (int l = 0; l < 16; l++) v += __ldg(&Mj[l]) * (ui[l] - uj[l]);

        const float wk = ui[k] - uj[k];
        float p = wk * v;
        p += __shfl_xor_sync(0xffffffffu, p, 8);
        p += __shfl_xor_sync(0xffffffffu, p, 4);
        p += __shfl_xor_sync(0xffffffffu, p, 2);
        p += __shfl_xor_sync(0xffffffffu, p, 1);
        const float kl = 0.5f * p;

        const float bj  = beta_sh[j];
        const float bkl = bj * kl;
        s1 += bj * v;
        s2 += bkl * v;
        s3 += bkl;
    }

    red1[hw][k] = s1;
    red2[hw][k] = s2;
    if (k == 0) red3[hw] = s3;
    __syncthreads();

    if (tid < 16) {
        float S1 = 0.f, S2 = 0.f, S3 = 0.f;
        #pragma unroll
        for (int h = 0; h < 8; h++) {
            S1 += red1[h][tid];
            S2 += red2[h][tid];
            S3 += red3[h];
        }
        t_sh[tid] = LAM * S1 + (LAM / KAPPA) * (S2 - S3 * S1);
    }
    __syncthreads();

    if (tid < 16) {
        const int node = b * N_ + i;
        const float* Ei = E_g + node * 256;
        float g = 0.f;
        #pragma unroll
        for (int l = 0; l < 16; l++) g += Ei[tid*16 + l] * t_sh[l];

        const float sp = fmaxf(__ldg(&sigma_p[node*16 + tid]), EPS);
        const float sq = fmaxf(__ldg(&sigma_q[node*16 + tid]), EPS);
        const float dm = __ldg(&mu_q[node*16 + tid]) - __ldg(&mu_p[node*16 + tid]);

        out[node*16 + tid]                 = g + ALPHA * dm / sp;
        out[NODES*K_ + node*16 + tid]      = ALPHA * 0.5f * (1.0f / sp - 1.0f / sq);
    }
}

extern "C" void kernel_launch(void* const* d_in, const int* in_sizes, int n_in,
                              void* d_out, int out_size)
{
    const float* mu_q    = (const float*)d_in[0];
    const float* sigma_q = (const float*)d_in[1];
    const float* mu_p    = (const float*)d_in[2];
    const float* sigma_p = (const float*)d_in[3];
    const float* beta    = (const float*)d_in[4];
    const float* phi     = (const float*)d_in[5];
    const float* gen     = (const float*)d_in[6];
    float* out = (float*)d_out;

    prep_kernel<<<NODES, 256>>>(mu_q, sigma_q, phi, gen);
    pair_kernel<<<NODES, 128>>>(mu_q, sigma_q, mu_p, sigma_p, beta, out);
}

// round 2
// speedup vs baseline: 2.6177x; 2.6177x over previous
#include <cuda_runtime.h>
#include <cuda_bf16.h>
#include <math.h>

// Problem constants
#define B_    8
#define N_    128
#define K_    16
#define ALPHA 0.01f
#define LAM   1.0f
#define KAPPA 1.0f
#define EPS   1e-6f

#define NODES (B_ * N_)   // 1024

// Scratch (device globals — no allocation allowed)
// M_g layout per node: [l4][k][c]  (l4=col-chunk 0..3, k=row 0..15, c=0..3)
// so that float4 index (node*64 + l4*16 + k) == M[k][4*l4+c], lane-coalesced.
__device__ __align__(16) float E_g[NODES * K_ * K_];
__device__ __align__(16) float M_g[NODES * K_ * K_];
__device__ __align__(16) float u_g[NODES * K_];

// ---------------------------------------------------------------------------
// Kernel 1: per-node precompute.
// A = sum_a phi[a] * G[a]  (antisymmetric 16x16)
// E = expm(A) via scaling-and-squaring + Taylor(9), threshold 0.35
// u = E^T mu_q,  M = E^T diag(1/(clip(sigma_q)+eps)) E   (permuted layout)
// ---------------------------------------------------------------------------
__global__ __launch_bounds__(256, 6)
void prep_kernel(const float* __restrict__ mu_q,
                 const float* __restrict__ sigma_q,
                 const float* __restrict__ phi,
                 const float* __restrict__ gen)
{
    const int node = blockIdx.x;
    const int tid  = threadIdx.x;          // 0..255
    const int r = tid >> 4, c = tid & 15;

    __shared__ float A [16][17];
    __shared__ float X [16][17];
    __shared__ float Y [16][17];
    __shared__ float rowsum[16];
    __shared__ int   s_shift;
    __shared__ float dinv[16];
    __shared__ float mush[16];

    const float p0 = __ldg(&phi[node*3 + 0]);
    const float p1 = __ldg(&phi[node*3 + 1]);
    const float p2 = __ldg(&phi[node*3 + 2]);
    const float a_raw = p0 * __ldg(&gen[0*256 + tid])
                      + p1 * __ldg(&gen[1*256 + tid])
                      + p2 * __ldg(&gen[2*256 + tid]);
    A[r][c] = a_raw;
    __syncthreads();

    // inf-norm for scaling
    if (tid < 16) {
        float s = 0.f;
        #pragma unroll
        for (int l = 0; l < 16; l++) s += fabsf(A[tid][l]);
        rowsum[tid] = s;
    }
    __syncthreads();
    if (tid == 0) {
        float nrm = 0.f;
        #pragma unroll
        for (int l = 0; l < 16; l++) nrm = fmaxf(nrm, rowsum[l]);
        int s = 0;
        while (nrm > 0.35f && s < 30) { nrm *= 0.5f; s++; }
        s_shift = s;
    }
    __syncthreads();
    const int   s_sq  = s_shift;
    const float scale = ldexpf(1.0f, -s_sq);

    A[r][c] = a_raw * scale;

    // Taylor-9 Horner:  X = I + B/9 ; X = I + (B/m) X, m = 8..1
    const int q = 9;
    __syncthreads();
    X[r][c] = (r == c ? 1.0f : 0.0f) + A[r][c] * (1.0f / (float)q);
    __syncthreads();

    float* Xp = &X[0][0];
    float* Yp = &Y[0][0];
    for (int m = q - 1; m >= 1; m--) {
        const float inv = 1.0f / (float)m;
        float acc = 0.f;
        #pragma unroll
        for (int l = 0; l < 16; l++) acc += A[r][l] * Xp[l*17 + c];
        Yp[r*17 + c] = (r == c ? 1.0f : 0.0f) + inv * acc;
        __syncthreads();
        float* t = Xp; Xp = Yp; Yp = t;
    }

    // squaring
    for (int t = 0; t < s_sq; t++) {
        float acc = 0.f;
        #pragma unroll
        for (int l = 0; l < 16; l++) acc += Xp[r*17 + l] * Xp[l*17 + c];
        Yp[r*17 + c] = acc;
        __syncthreads();
        float* tt = Xp; Xp = Yp; Yp = tt;
    }
    // Xp == E (row-major in shared, stride 17)

    if (tid < 16) {
        const float sq = fmaxf(__ldg(&sigma_q[node*16 + tid]), EPS);
        dinv[tid] = 1.0f / (sq + EPS);
        mush[tid] = __ldg(&mu_q[node*16 + tid]);
    }
    __syncthreads();

    // M = E^T D^{-1} E,  stored permuted: [l4][k][cc]
    {
        float acc = 0.f;
        #pragma unroll
        for (int l = 0; l < 16; l++) acc += Xp[l*17 + r] * dinv[l] * Xp[l*17 + c];
        const int l4 = c >> 2, cc = c & 3;
        M_g[node*256 + l4*64 + r*4 + cc] = acc;
        E_g[node*256 + r*16 + c] = Xp[r*17 + c];
    }
    // u = E^T mu
    if (tid < 16) {
        float uu = 0.f;
        #pragma unroll
        for (int l = 0; l < 16; l++) uu += Xp[l*17 + tid] * mush[l];
        u_g[node*16 + tid] = uu;
    }
}

// ---------------------------------------------------------------------------
// Kernel 2: pair reduction. One block per (b, i); 128 threads = 8 half-warps.
// Half-warp hw owns j = iter*8 + hw; lane k = component/row.
//   v_k   = M_j[k][:] . (u_i - u_j)       (4x LDG.128, lane-coalesced)
//   kl    = 0.5 * sum_k w_k v_k           (shfl-16 reduce)
//   S1   += beta v ; S2 += beta kl v ; s3 += beta kl
// Epilogue: t = LAM*S1 + (LAM/KAPPA)*(S2 - s3*S1); grad_mu = self + E_i t.
// ---------------------------------------------------------------------------
__global__ __launch_bounds__(128, 8)
void pair_kernel(const float* __restrict__ mu_q,
                 const float* __restrict__ sigma_q,
                 const float* __restrict__ mu_p,
                 const float* __restrict__ sigma_p,
                 const float* __restrict__ beta,
                 float* __restrict__ out)
{
    const int blk = blockIdx.x;
    const int b   = blk >> 7;
    const int i   = blk & 127;
    const int tid = threadIdx.x;       // 0..127

    __shared__ __align__(16) float u_sh[N_ * K_];    // 8 KB
    __shared__ float beta_sh[N_];
    __shared__ float red1[8][16];
    __shared__ float red2[8][16];
    __shared__ float red3[8];
    __shared__ float t_sh[16];

    float4* u_sh4 = (float4*)u_sh;
    const float4* ub4 = (const float4*)(u_g + b * N_ * K_);
    #pragma unroll
    for (int idx = tid; idx < N_ * K_ / 4; idx += 128) u_sh4[idx] = ub4[idx];
    beta_sh[tid] = __ldg(&beta[(b * N_ + i) * N_ + tid]);
    __syncthreads();

    const int k  = tid & 15;           // component / row
    const int hw = tid >> 4;           // half-warp id 0..7

    const float4 ui0 = u_sh4[i*4 + 0];
    const float4 ui1 = u_sh4[i*4 + 1];
    const float4 ui2 = u_sh4[i*4 + 2];
    const float4 ui3 = u_sh4[i*4 + 3];
    const float  ui_k = u_sh[i*16 + k];

    float s1 = 0.f, s2 = 0.f, s3 = 0.f;
    const float4* Mb4 = (const float4*)(M_g + b * N_ * 256);

    #pragma unroll 2
    for (int iter = 0; iter < 16; iter++) {
        const int j = iter * 8 + hw;
        const float4* Mj = Mb4 + j * 64;

        // M row k, 4 column-chunks — lane-coalesced float4 loads
        const float4 m0 = __ldg(&Mj[ 0 + k]);
        const float4 m1 = __ldg(&Mj[16 + k]);
        const float4 m2 = __ldg(&Mj[32 + k]);
        const float4 m3 = __ldg(&Mj[48 + k]);

        const float4 uj0 = u_sh4[j*4 + 0];
        const float4 uj1 = u_sh4[j*4 + 1];
        const float4 uj2 = u_sh4[j*4 + 2];
        const float4 uj3 = u_sh4[j*4 + 3];

        float4 w0, w1, w2, w3;
        w0.x = ui0.x - uj0.x; w0.y = ui0.y - uj0.y; w0.z = ui0.z - uj0.z; w0.w = ui0.w - uj0.w;
        w1.x = ui1.x - uj1.x; w1.y = ui1.y - uj1.y; w1.z = ui1.z - uj1.z; w1.w = ui1.w - uj1.w;
        w2.x = ui2.x - uj2.x; w2.y = ui2.y - uj2.y; w2.z = ui2.z - uj2.z; w2.w = ui2.w - uj2.w;
        w3.x = ui3.x - uj3.x; w3.y = ui3.y - uj3.y; w3.z = ui3.z - uj3.z; w3.w = ui3.w - uj3.w;

        float v = m0.x * w0.x;
        v = fmaf(m0.y, w0.y, v); v = fmaf(m0.z, w0.z, v); v = fmaf(m0.w, w0.w, v);
        v = fmaf(m1.x, w1.x, v); v = fmaf(m1.y, w1.y, v); v = fmaf(m1.z, w1.z, v); v = fmaf(m1.w, w1.w, v);
        v = fmaf(m2.x, w2.x, v); v = fmaf(m2.y, w2.y, v); v = fmaf(m2.z, w2.z, v); v = fmaf(m2.w, w2.w, v);
        v = fmaf(m3.x, w3.x, v); v = fmaf(m3.y, w3.y, v); v = fmaf(m3.z, w3.z, v); v = fmaf(m3.w, w3.w, v);

        const float wk = ui_k - u_sh[j*16 + k];
        float p = wk * v;
        p += __shfl_xor_sync(0xffffffffu, p, 8);
        p += __shfl_xor_sync(0xffffffffu, p, 4);
        p += __shfl_xor_sync(0xffffffffu, p, 2);
        p += __shfl_xor_sync(0xffffffffu, p, 1);
        const float kl = 0.5f * p;

        const float bj  = beta_sh[j];
        const float bkl = bj * kl;
        s1 = fmaf(bj,  v, s1);
        s2 = fmaf(bkl, v, s2);
        s3 += bkl;
    }

    red1[hw][k] = s1;
    red2[hw][k] = s2;
    if (k == 0) red3[hw] = s3;
    __syncthreads();

    if (tid < 16) {
        float S1 = 0.f, S2 = 0.f, S3 = 0.f;
        #pragma unroll
        for (int h = 0; h < 8; h++) {
            S1 += red1[h][tid];
            S2 += red2[h][tid];
            S3 += red3[h];
        }
        t_sh[tid] = LAM * S1 + (LAM / KAPPA) * (S2 - S3 * S1);
    }
    __syncthreads();

    if (tid < 16) {
        const int node = b * N_ + i;
        const float* Ei = E_g + node * 256;
        float g = 0.f;
        #pragma unroll
        for (int l = 0; l < 16; l++) g += Ei[tid*16 + l] * t_sh[l];

        const float sp = fmaxf(__ldg(&sigma_p[node*16 + tid]), EPS);
        const float sq = fmaxf(__ldg(&sigma_q[node*16 + tid]), EPS);
        const float dm = __ldg(&mu_q[node*16 + tid]) - __ldg(&mu_p[node*16 + tid]);

        out[node*16 + tid]                 = g + ALPHA * dm / sp;
        out[NODES*K_ + node*16 + tid]      = ALPHA * 0.5f * (1.0f / sp - 1.0f / sq);
    }
}

extern "C" void kernel_launch(void* const* d_in, const int* in_sizes, int n_in,
                              void* d_out, int out_size)
{
    const float* mu_q    = (const float*)d_in[0];
    const float* sigma_q = (const float*)d_in[1];
    const float* mu_p    = (const float*)d_in[2];
    const float* sigma_p = (const float*)d_in[3];
    const float* beta    = (const float*)d_in[4];
    const float* phi     = (const float*)d_in[5];
    const float* gen     = (const float*)d_in[6];
    float* out = (float*)d_out;

    prep_kernel<<<NODES, 256>>>(mu_q, sigma_q, phi, gen);
    pair_kernel<<<NODES, 128>>>(mu_q, sigma_q, mu_p, sigma_p, beta, out);
}